// round 11
// baseline (speedup 1.0000x reference)
#include <cuda_runtime.h>
#include <cstddef>

constexpr int cNU = 100000, cNM = 20000, cH = 64, cE = 1000000, cEL = 500000;
constexpr int NBU = 98, NBM = 20;

// ---- device scratch ----
__device__ float g_xu0[cNU * cH];
__device__ float g_cat_u[cNU * 192];
__device__ float g_cat_m[cNM * 192];
__device__ float g_agg_u[cNU * cH];
__device__ float g_agg_m[cNM * cH];
__device__ float g_ym[cNM * cH];
__device__ float g_hu[cNU * cH];
__device__ float g_hm[cNM * cH];
__device__ float g_z2[(size_t)cEL * 32];
__device__ int g_cnt_u[cNU], g_cnt_m[cNM], g_pos_u[cNU], g_pos_m[cNM];
__device__ int g_off_u[cNU + 1], g_off_m[cNM + 1];
__device__ int g_adj_u[cE], g_adj_m[cE];
__device__ int g_aux[128], g_aux2[128];
__device__ double g_stats[192];
__device__ float g_bnp[192];
__device__ float g_wfu[192 * 64], g_wfm[192 * 64], g_bfu[64], g_bfm[64];

constexpr int CNTB = (cE + 255) / 256;          // 3907
constexpr int GATB = (cNU * 16 + 255) / 256;    // 6250
constexpr int MB = (cNM + 127) / 128;           // 157
constexpr int UB = (cNU + 127) / 128;           // 782
constexpr int AGGMB = cNM * 32 / 256;           // 2500
constexpr int AGGUB = cNU * 32 / 256;           // 12500

__global__ void zero_kernel() {
    int i = blockIdx.x * blockDim.x + threadIdx.x;
    if (i < cNU) { g_cnt_u[i] = 0; g_pos_u[i] = 0; }
    if (i < cNM) { g_cnt_m[i] = 0; g_pos_m[i] = 0; }
    if (i < 192) g_stats[i] = 0.0;
}

// count + gather_u0 + wfuse, one launch (independent work)
__global__ void __launch_bounds__(256) prep_kernel(
    const int* __restrict__ eu, const int* __restrict__ em,
    const int* __restrict__ n_id, const float* __restrict__ ue,
    const float* __restrict__ puW, const float* __restrict__ pub,
    const float* __restrict__ pmW, const float* __restrict__ pmb,
    const float* __restrict__ W1, const float* __restrict__ b1) {
    int bid = blockIdx.x, tid = threadIdx.x;
    if (bid < CNTB) {
        int e = bid * 256 + tid;
        if (e < cE) { atomicAdd(&g_cnt_u[eu[e]], 1); atomicAdd(&g_cnt_m[em[e]], 1); }
    } else if (bid < CNTB + GATB) {
        int i = (bid - CNTB) * 256 + tid;
        if (i < cNU * 16) {
            int r = i >> 4, c = i & 15;
            ((float4*)g_xu0)[r * 16 + c] = ((const float4*)ue)[(size_t)n_id[r] * 16 + c];
        }
    } else {
        int b = bid - CNTB - GATB;  // 0..384
        int c = tid;
        if (c < 64) {
            if (b < 192) {
                float s = 0.f;
                for (int k = 0; k < 64; ++k) s += puW[b * 64 + k] * W1[k * 64 + c];
                g_wfu[b * 64 + c] = s;
            } else if (b < 384) {
                int r = b - 192;
                float s = 0.f;
                for (int k = 0; k < 64; ++k) s += pmW[r * 64 + k] * W1[(64 + k) * 64 + c];
                g_wfm[r * 64 + c] = s;
            } else {
                float su = 0.f, sm2 = 0.f;
                for (int k = 0; k < 64; ++k) {
                    su += pub[k] * W1[k * 64 + c];
                    sm2 += pmb[k] * W1[(64 + k) * 64 + c];
                }
                g_bfu[c] = su + b1[c];
                g_bfm[c] = sm2;
            }
        }
    }
}

__global__ void __launch_bounds__(1024) scan1_kernel() {
    __shared__ int s[1024];
    int b = blockIdx.x, t = threadIdx.x;
    const int* cnt; int* off; int n, base;
    if (b < NBU) { cnt = g_cnt_u; off = g_off_u; n = cNU; base = b * 1024; }
    else         { cnt = g_cnt_m; off = g_off_m; n = cNM; base = (b - NBU) * 1024; }
    int i = base + t;
    int v = (i < n) ? cnt[i] : 0;
    int x = v;
    for (int d = 1; d < 1024; d <<= 1) {
        s[t] = x; __syncthreads();
        if (t >= d) x += s[t - d];
        __syncthreads();
    }
    if (i < n) off[i] = x - v;
    if (t == 1023) g_aux[b] = x;
}

__global__ void __launch_bounds__(128) scan2_kernel() {
    __shared__ int s[128];
    int t = threadIdx.x;
    int base = blockIdx.x ? NBU : 0, n = blockIdx.x ? NBM : NBU;
    int v = (t < n) ? g_aux[base + t] : 0;
    int x = v;
    for (int d = 1; d < 128; d <<= 1) {
        s[t] = x; __syncthreads();
        if (t >= d) x += s[t - d];
        __syncthreads();
    }
    if (t < n) g_aux2[base + t] = x - v;
}

__global__ void scan3_kernel() {
    int i = blockIdx.x * blockDim.x + threadIdx.x;
    if (i < cNU) g_off_u[i] += g_aux2[i >> 10];
    int j = i - cNU;
    if (j >= 0 && j < cNM) g_off_m[j] += g_aux2[NBU + (j >> 10)];
    if (i == 0) { g_off_u[cNU] = cE; g_off_m[cNM] = cE; }
}

__global__ void fill_kernel(const int* __restrict__ eu, const int* __restrict__ em) {
    int e = blockIdx.x * blockDim.x + threadIdx.x;
    if (e < cE) {
        int u = eu[e], m = em[e];
        g_adj_m[g_off_m[m] + atomicAdd(&g_pos_m[m], 1)] = u;
        g_adj_u[g_off_u[u] + atomicAdd(&g_pos_u[u], 1)] = m;
    }
}

__device__ __forceinline__ void agg_row(const float* __restrict__ src, int lds,
                                        const int* __restrict__ adj, int beg, int end,
                                        float* __restrict__ dst, int lane) {
    float ax = 0.f, ay = 0.f;
#pragma unroll 4
    for (int e = beg; e < end; ++e) {
        int s = __ldg(adj + e);
        float2 v = *(const float2*)(src + (size_t)s * lds + lane * 2);
        ax += v.x; ay += v.y;
    }
    float inv = (end > beg) ? 1.f / (float)(end - beg) : 0.f;
    *(float2*)(dst + lane * 2) = make_float2(ax * inv, ay * inv);
}

// ---- stage weights [K][N] -> k-pair-interleaved float2 smem ----
template <int K, int N>
__device__ __forceinline__ void stageWpair(float2* sWp, const float* __restrict__ W, int tid) {
    constexpr int NITEMS = (K / 2) * (N / 4);
    for (int idx = tid; idx < NITEMS; idx += 256) {
        int k2 = idx / (N / 4);
        int j4 = (idx - k2 * (N / 4)) * 4;
        float4 r0 = *(const float4*)(W + (size_t)(2 * k2) * N + j4);
        float4 r1 = *(const float4*)(W + (size_t)(2 * k2 + 1) * N + j4);
        float2* d = sWp + k2 * N + j4;
        d[0] = make_float2(r0.x, r1.x);
        d[1] = make_float2(r0.y, r1.y);
        d[2] = make_float2(r0.z, r1.z);
        d[3] = make_float2(r0.w, r1.w);
    }
}

// ---- GEMM core, 256 threads, FFMA2 ----
template <int K, int N>
__device__ __forceinline__ void gemm_x2(const float* __restrict__ sA,
                                        const float2* __restrict__ sWp,
                                        float acc[4][N / 8]) {
    constexpr int LDA = K + 2, CPT = N / 8;
    const int rowg = threadIdx.x & 31, colg = threadIdx.x >> 5;
    const float* aB = sA + rowg * LDA;
    const float2* wB = sWp + colg * CPT;
    unsigned long long accp[4][CPT];
#pragma unroll
    for (int i = 0; i < 4; ++i)
#pragma unroll
        for (int j = 0; j < CPT; ++j) accp[i][j] = 0ull;
#pragma unroll 4
    for (int k2 = 0; k2 < K / 2; ++k2) {
        unsigned long long a[4], w[CPT];
#pragma unroll
        for (int i = 0; i < 4; ++i)
            a[i] = *(const unsigned long long*)(aB + i * 32 * LDA + k2 * 2);
#pragma unroll
        for (int j = 0; j < CPT; ++j)
            w[j] = *(const unsigned long long*)(wB + k2 * N + j);
#pragma unroll
        for (int i = 0; i < 4; ++i)
#pragma unroll
            for (int j = 0; j < CPT; ++j)
                asm("fma.rn.f32x2 %0, %1, %2, %0;" : "+l"(accp[i][j]) : "l"(a[i]), "l"(w[j]));
    }
#pragma unroll
    for (int i = 0; i < 4; ++i)
#pragma unroll
        for (int j = 0; j < CPT; ++j) {
            unsigned int lo = (unsigned int)accp[i][j];
            unsigned int hi = (unsigned int)(accp[i][j] >> 32);
            acc[i][j] = __uint_as_float(lo) + __uint_as_float(hi);
        }
}

constexpr int SAGE_SMEM = (128 * 130) * 4 + 64 * 64 * 8;   // 99328
constexpr int U64_SMEM  = (128 * 66) * 4 + 32 * 64 * 8;    // 50176
constexpr int PROJ_SMEM = (128 * 194) * 4 + 96 * 64 * 8;   // 148480
constexpr int Z2_SMEM   = (128 * 66) * 4 + 32 * 32 * 8;    // 41984

__device__ __forceinline__ void stageA64(float* sA, const float* __restrict__ x, int ldx,
                                         int rowbase, int nrows, int tid) {
    for (int idx = tid; idx < 128 * 32; idx += 256) {
        int r = idx >> 5, c2 = idx & 31, g = rowbase + r, c = c2 * 2;
        float2 v = make_float2(0.f, 0.f);
        if (g < nrows) v = *(const float2*)(x + (size_t)g * ldx + c);
        *(float2*)(sA + r * 66 + c) = v;
    }
}

// Kernel A: blocks [0,MB) = linear64 (ym = x_m @ Wl_mu); blocks [MB,MB+AGGMB) = movie-dst agg
__global__ void __launch_bounds__(256) linagg_kernel(const float* __restrict__ xm, int ldm,
                                                     const float* __restrict__ W,
                                                     const float* __restrict__ xu, int ldu) {
    extern __shared__ float sm[];
    const int tid = threadIdx.x;
    if ((int)blockIdx.x < MB) {
        float* sA = sm;
        float2* sWp = (float2*)(sm + 128 * 66);
        const int rowbase = blockIdx.x * 128;
        stageWpair<64, 64>(sWp, W, tid);
        stageA64(sA, xm, ldm, rowbase, cNM, tid);
        __syncthreads();
        float acc[4][8];
        gemm_x2<64, 64>(sA, sWp, acc);
        const int rowg = tid & 31, colg = tid >> 5;
#pragma unroll
        for (int i = 0; i < 4; ++i) {
            int g = rowbase + rowg + 32 * i;
            if (g < cNM) {
                float* dst = g_ym + (size_t)g * 64 + colg * 8;
                *(float4*)dst = make_float4(acc[i][0], acc[i][1], acc[i][2], acc[i][3]);
                *(float4*)(dst + 4) = make_float4(acc[i][4], acc[i][5], acc[i][6], acc[i][7]);
            }
        }
    } else {
        int w = (blockIdx.x - MB) * 8 + (tid >> 5);
        int lane = tid & 31;
        if (w < cNM)
            agg_row(xu, ldu, g_adj_m, g_off_m[w], g_off_m[w + 1], g_agg_m + (size_t)w * 64, lane);
    }
}

// Kernel B: user-dst aggregation of ym
__global__ void __launch_bounds__(256) aggu_kernel() {
    int w = (blockIdx.x * blockDim.x + threadIdx.x) >> 5;
    int lane = threadIdx.x & 31;
    if (w < cNU)
        agg_row(g_ym, 64, g_adj_u, g_off_u[w], g_off_u[w + 1], g_agg_u + (size_t)w * 64, lane);
}

// Kernel C: blocks [0,MB) movie sage; [MB,MB+UB) user sage
__global__ void __launch_bounds__(256) sage_both_kernel(
    const float* __restrict__ xm, int ldm, const float* __restrict__ xu, int ldu,
    const float* __restrict__ Wl_um, const float* __restrict__ Wr_um,
    const float* __restrict__ b_um,
    const float* __restrict__ Wr_mu, const float* __restrict__ b_mu,
    float* __restrict__ out_m, float* __restrict__ out_u) {
    extern __shared__ float sm[];
    __shared__ float sB[64];
    const int tid = threadIdx.x;
    const int rowg = tid & 31, colg = tid >> 5;
    if ((int)blockIdx.x < MB) {
        constexpr int LDA = 130;
        float* sA = sm;
        float2* sWp = (float2*)(sm + 128 * LDA);
        const int rowbase = blockIdx.x * 128;
        if (tid < 64) sB[tid] = b_um[tid];
        stageWpair<64, 64>(sWp, Wl_um, tid);
        stageWpair<64, 64>(sWp + 32 * 64, Wr_um, tid);
        for (int idx = tid; idx < 128 * 64; idx += 256) {
            int r = idx >> 6, c2 = idx & 63, g = rowbase + r, c = c2 * 2;
            float2 v = make_float2(0.f, 0.f);
            if (g < cNM)
                v = (c < 64) ? *(const float2*)(g_agg_m + (size_t)g * 64 + c)
                             : *(const float2*)(xm + (size_t)g * ldm + (c - 64));
            *(float2*)(sA + r * LDA + c) = v;
        }
        __syncthreads();
        float acc[4][8];
        gemm_x2<128, 64>(sA, sWp, acc);
#pragma unroll
        for (int i = 0; i < 4; ++i) {
            int g = rowbase + rowg + 32 * i;
            if (g < cNM) {
                float o[8];
#pragma unroll
                for (int j = 0; j < 8; ++j) o[j] = fmaxf(acc[i][j] + sB[colg * 8 + j], 0.f);
                float* dst = out_m + (size_t)g * 192 + colg * 8;
                *(float4*)dst = make_float4(o[0], o[1], o[2], o[3]);
                *(float4*)(dst + 4) = make_float4(o[4], o[5], o[6], o[7]);
            }
        }
    } else {
        float* sA = sm;
        float2* sWp = (float2*)(sm + 128 * 66);
        const int rowbase = (blockIdx.x - MB) * 128;
        if (tid < 64) sB[tid] = b_mu[tid];
        stageWpair<64, 64>(sWp, Wr_mu, tid);
        stageA64(sA, xu, ldu, rowbase, cNU, tid);
        __syncthreads();
        float acc[4][8];
        gemm_x2<64, 64>(sA, sWp, acc);
#pragma unroll
        for (int i = 0; i < 4; ++i) {
            int g = rowbase + rowg + 32 * i;
            if (g < cNU) {
                const float* ag = g_agg_u + (size_t)g * 64 + colg * 8;
                float4 a0 = *(const float4*)ag, a1 = *(const float4*)(ag + 4);
                float o[8];
                o[0] = fmaxf(acc[i][0] + a0.x + sB[colg * 8 + 0], 0.f);
                o[1] = fmaxf(acc[i][1] + a0.y + sB[colg * 8 + 1], 0.f);
                o[2] = fmaxf(acc[i][2] + a0.z + sB[colg * 8 + 2], 0.f);
                o[3] = fmaxf(acc[i][3] + a0.w + sB[colg * 8 + 3], 0.f);
                o[4] = fmaxf(acc[i][4] + a1.x + sB[colg * 8 + 4], 0.f);
                o[5] = fmaxf(acc[i][5] + a1.y + sB[colg * 8 + 5], 0.f);
                o[6] = fmaxf(acc[i][6] + a1.z + sB[colg * 8 + 6], 0.f);
                o[7] = fmaxf(acc[i][7] + a1.w + sB[colg * 8 + 7], 0.f);
                float* dst = out_u + (size_t)g * 192 + colg * 8;
                *(float4*)dst = make_float4(o[0], o[1], o[2], o[3]);
                *(float4*)(dst + 4) = make_float4(o[4], o[5], o[6], o[7]);
            }
        }
    }
}

// combined proj: blocks [0,UB) users, [UB,UB+MB) movies
__global__ void __launch_bounds__(256) proj_gemm_kernel() {
    constexpr int LDA = 194;
    extern __shared__ float sm[];
    float* sA = sm;
    float2* sWp = (float2*)(sm + 128 * LDA);
    __shared__ float sB[64];
    const int tid = threadIdx.x;
    bool isU = (int)blockIdx.x < UB;
    const float* A = isU ? g_cat_u : g_cat_m;
    const float* W = isU ? g_wfu : g_wfm;
    const float* bias = isU ? g_bfu : g_bfm;
    float* outp = isU ? g_hu : g_hm;
    int nrows = isU ? cNU : cNM;
    int rowbase = (isU ? blockIdx.x : (blockIdx.x - UB)) * 128;
    if (tid < 64) sB[tid] = bias[tid];
    stageWpair<192, 64>(sWp, W, tid);
    for (int idx = tid; idx < 128 * 96; idx += 256) {
        int r = idx / 96, c2 = idx - r * 96, g = rowbase + r;
        float2 v = make_float2(0.f, 0.f);
        if (g < nrows) v = *(const float2*)(A + (size_t)g * 192 + c2 * 2);
        *(float2*)(sA + r * LDA + c2 * 2) = v;
    }
    __syncthreads();
    float acc[4][8];
    gemm_x2<192, 64>(sA, sWp, acc);
    const int rowg = tid & 31, colg = tid >> 5;
#pragma unroll
    for (int i = 0; i < 4; ++i) {
        int g = rowbase + rowg + 32 * i;
        if (g < nrows) {
            float o[8];
#pragma unroll
            for (int j = 0; j < 8; ++j) o[j] = acc[i][j] + sB[colg * 8 + j];
            float* dst = outp + (size_t)g * 64 + colg * 8;
            *(float4*)dst = make_float4(o[0], o[1], o[2], o[3]);
            *(float4*)(dst + 4) = make_float4(o[4], o[5], o[6], o[7]);
        }
    }
}

__global__ void __launch_bounds__(256) z1stats_kernel(const int* __restrict__ lu,
                                                      const int* __restrict__ lm) {
    __shared__ float sS[64], sQ[64];
    int tid = threadIdx.x;
    if (tid < 64) { sS[tid] = 0.f; sQ[tid] = 0.f; }
    __syncthreads();
    int lane = tid & 31;
    int gw = (blockIdx.x * 256 + tid) >> 5;
    int nw = gridDim.x * 8;
    float s0 = 0.f, s1 = 0.f, q0 = 0.f, q1 = 0.f;
    for (int r = gw; r < cEL; r += nw) {
        int u = __ldg(lu + r), m = __ldg(lm + r);
        float2 a = *(const float2*)(g_hu + (size_t)u * 64 + lane * 2);
        float2 b = *(const float2*)(g_hm + (size_t)m * 64 + lane * 2);
        float ox = a.x + b.x, oy = a.y + b.y;
        s0 += ox; s1 += oy; q0 += ox * ox; q1 += oy * oy;
    }
    atomicAdd(&sS[lane * 2], s0); atomicAdd(&sS[lane * 2 + 1], s1);
    atomicAdd(&sQ[lane * 2], q0); atomicAdd(&sQ[lane * 2 + 1], q1);
    __syncthreads();
    if (tid < 64) {
        atomicAdd(&g_stats[tid], (double)sS[tid]);
        atomicAdd(&g_stats[64 + tid], (double)sQ[tid]);
    }
}

__global__ void bn_finalize_kernel(int soff, int boff, int n,
                                   const float* __restrict__ gamma,
                                   const float* __restrict__ beta, float invc) {
    int t = threadIdx.x;
    if (t < n) {
        double m = g_stats[soff + t] * invc;
        double v = g_stats[soff + n + t] * invc - m * m;
        float sc = gamma[t] * rsqrtf((float)v + 1e-5f);
        g_bnp[boff + t] = sc;
        g_bnp[boff + n + t] = beta[t] - (float)m * sc;
    }
}

__global__ void __launch_bounds__(256) z2_kernel(const int* __restrict__ lu,
                                                 const int* __restrict__ lm,
                                                 const float* __restrict__ W2,
                                                 const float* __restrict__ bias) {
    constexpr int LDA = 66;
    extern __shared__ float sm[];
    float* sA = sm;
    float2* sWp = (float2*)(sm + 128 * LDA);
    __shared__ float sB[32], sSc[64], sSh[64];
    __shared__ int sIU[128], sIM[128];
    const int tid = threadIdx.x, rowbase = blockIdx.x * 128;
    if (tid < 32) sB[tid] = bias[tid];
    if (tid < 64) { sSc[tid] = g_bnp[tid]; sSh[tid] = g_bnp[64 + tid]; }
    if (tid < 128) {
        int g = rowbase + tid;
        sIU[tid] = (g < cEL) ? __ldg(lu + g) : 0;
        sIM[tid] = (g < cEL) ? __ldg(lm + g) : 0;
    }
    stageWpair<64, 32>(sWp, W2, tid);
    __syncthreads();
    for (int idx = tid; idx < 128 * 32; idx += 256) {
        int r = idx >> 5, c2 = idx & 31, g = rowbase + r, c = c2 * 2;
        float2 v = make_float2(0.f, 0.f);
        if (g < cEL) {
            float2 a = *(const float2*)(g_hu + (size_t)sIU[r] * 64 + c);
            float2 b = *(const float2*)(g_hm + (size_t)sIM[r] * 64 + c);
            float zx = a.x + b.x, zy = a.y + b.y;
            v.x = fmaxf(zx * sSc[c] + sSh[c], 0.f);
            v.y = fmaxf(zy * sSc[c + 1] + sSh[c + 1], 0.f);
        }
        *(float2*)(sA + r * LDA + c) = v;
    }
    __syncthreads();
    float acc[4][4];
    gemm_x2<64, 32>(sA, sWp, acc);
    const int rowg = tid & 31, colg = tid >> 5;
    float ls[4] = {0}, lq[4] = {0};
#pragma unroll
    for (int i = 0; i < 4; ++i) {
        int g = rowbase + rowg + 32 * i;
        if (g < cEL) {
            float o[4];
#pragma unroll
            for (int j = 0; j < 4; ++j) {
                o[j] = acc[i][j] + sB[colg * 4 + j];
                ls[j] += o[j]; lq[j] += o[j] * o[j];
            }
            *(float4*)(g_z2 + (size_t)g * 32 + colg * 4) = make_float4(o[0], o[1], o[2], o[3]);
        }
    }
    __syncthreads();
#pragma unroll
    for (int j = 0; j < 4; ++j) {
        sA[rowg * 32 + colg * 4 + j] = ls[j];
        sA[1024 + rowg * 32 + colg * 4 + j] = lq[j];
    }
    __syncthreads();
    if (tid < 32) {
        float s = 0.f, q = 0.f;
        for (int g2 = 0; g2 < 32; ++g2) { s += sA[g2 * 32 + tid]; q += sA[1024 + g2 * 32 + tid]; }
        atomicAdd(&g_stats[128 + tid], (double)s);
        atomicAdd(&g_stats[160 + tid], (double)q);
    }
}

__global__ void __launch_bounds__(256) z3_kernel(const float* __restrict__ W3,
                                                 const float* __restrict__ b3,
                                                 float* __restrict__ out) {
    __shared__ float sW[32], sSc[32], sSh[32];
    int tid = threadIdx.x;
    if (tid < 32) { sW[tid] = W3[tid]; sSc[tid] = g_bnp[128 + tid]; sSh[tid] = g_bnp[160 + tid]; }
    __syncthreads();
    int g = blockIdx.x * 256 + tid;
    if (g < cEL) {
        const float* row = g_z2 + (size_t)g * 32;
        float acc = 0.f;
#pragma unroll
        for (int c = 0; c < 32; c += 4) {
            float4 v = *(const float4*)(row + c);
            acc += fmaxf(v.x * sSc[c] + sSh[c], 0.f) * sW[c];
            acc += fmaxf(v.y * sSc[c + 1] + sSh[c + 1], 0.f) * sW[c + 1];
            acc += fmaxf(v.z * sSc[c + 2] + sSh[c + 2], 0.f) * sW[c + 2];
            acc += fmaxf(v.w * sSc[c + 3] + sSh[c + 3], 0.f) * sW[c + 3];
        }
        out[g] = acc + b3[0];
    }
}

extern "C" void kernel_launch(void* const* d_in, const int* in_sizes, int n_in,
                              void* d_out, int out_size) {
    const int* n_id = (const int*)d_in[0];
    const float* movie_x = (const float*)d_in[1];
    const int* eu = (const int*)d_in[2];
    const int* em = (const int*)d_in[3];
    const int* lu = (const int*)d_in[4];
    const int* lm = (const int*)d_in[5];
    const float* user_emb = (const float*)d_in[6];
    const float* Wl_um = (const float*)d_in[7];
    const float* b_um = (const float*)d_in[8];
    const float* Wr_um = (const float*)d_in[9];
    const float* Wl_mu = (const float*)d_in[10];
    const float* b_mu = (const float*)d_in[11];
    const float* Wr_mu = (const float*)d_in[12];
    const float* proj_u_W = (const float*)d_in[13];
    const float* proj_u_b = (const float*)d_in[14];
    const float* proj_m_W = (const float*)d_in[15];
    const float* proj_m_b = (const float*)d_in[16];
    const float* W1 = (const float*)d_in[17];
    const float* b1 = (const float*)d_in[18];
    const float* g1 = (const float*)d_in[19];
    const float* be1 = (const float*)d_in[20];
    const float* W2 = (const float*)d_in[21];
    const float* b2 = (const float*)d_in[22];
    const float* g2 = (const float*)d_in[23];
    const float* be2 = (const float*)d_in[24];
    const float* W3 = (const float*)d_in[25];
    const float* b3 = (const float*)d_in[26];
    float* out = (float*)d_out;

    cudaFuncSetAttribute(linagg_kernel, cudaFuncAttributeMaxDynamicSharedMemorySize, U64_SMEM);
    cudaFuncSetAttribute(sage_both_kernel, cudaFuncAttributeMaxDynamicSharedMemorySize, SAGE_SMEM);
    cudaFuncSetAttribute(proj_gemm_kernel, cudaFuncAttributeMaxDynamicSharedMemorySize, PROJ_SMEM);
    cudaFuncSetAttribute(z2_kernel, cudaFuncAttributeMaxDynamicSharedMemorySize, Z2_SMEM);

    float* xu; cudaGetSymbolAddress((void**)&xu, g_xu0);
    float* cu; cudaGetSymbolAddress((void**)&cu, g_cat_u);
    float* cm; cudaGetSymbolAddress((void**)&cm, g_cat_m);

    zero_kernel<<<(cNU + 255) / 256, 256>>>();
    prep_kernel<<<CNTB + GATB + 385, 256>>>(eu, em, n_id, user_emb,
                                            proj_u_W, proj_u_b, proj_m_W, proj_m_b, W1, b1);
    scan1_kernel<<<NBU + NBM, 1024>>>();
    scan2_kernel<<<2, 128>>>();
    scan3_kernel<<<(cNU + cNM + 255) / 256, 256>>>();
    fill_kernel<<<(cE + 255) / 256, 256>>>(eu, em);

    for (int i = 0; i < 3; ++i) {
        const float* xup = i ? (cu + (i - 1) * 64) : xu;
        const float* xmp = i ? (cm + (i - 1) * 64) : movie_x;
        int ldu = i ? 192 : 64, ldm = i ? 192 : 64;
        linagg_kernel<<<MB + AGGMB, 256, U64_SMEM>>>(xmp, ldm, Wl_mu + i * 4096, xup, ldu);
        aggu_kernel<<<AGGUB, 256>>>();
        sage_both_kernel<<<MB + UB, 256, SAGE_SMEM>>>(
            xmp, ldm, xup, ldu, Wl_um + i * 4096, Wr_um + i * 4096, b_um + i * 64,
            Wr_mu + i * 4096, b_mu + i * 64, cm + i * 64, cu + i * 64);
    }
    proj_gemm_kernel<<<UB + MB, 256, PROJ_SMEM>>>();

    z1stats_kernel<<<1184, 256>>>(lu, lm);
    bn_finalize_kernel<<<1, 64>>>(0, 0, 64, g1, be1, 1.f / cEL);
    z2_kernel<<<(cEL + 127) / 128, 256, Z2_SMEM>>>(lu, lm, W2, b2);
    bn_finalize_kernel<<<1, 64>>>(128, 128, 32, g2, be2, 1.f / cEL);
    z3_kernel<<<(cEL + 255) / 256, 256>>>(W3, b3, out);
}

// round 13
// speedup vs baseline: 1.0097x; 1.0097x over previous
#include <cuda_runtime.h>
#include <cstddef>

constexpr int cNU = 100000, cNM = 20000, cH = 64, cE = 1000000, cEL = 500000;
constexpr int NBU = 98, NBM = 20;

// ---- device scratch ----
__device__ float g_xu0[cNU * cH];
__device__ float g_cat_u[cNU * 192];
__device__ float g_cat_m[cNM * 192];
__device__ float g_agg_u[cNU * cH];
__device__ float g_agg_m[cNM * cH];
__device__ float g_ym[cNM * cH];
__device__ float g_hu[cNU * cH];
__device__ float g_hm[cNM * cH];
__device__ float g_z2[(size_t)cEL * 32];
__device__ int g_cnt_u[cNU], g_cnt_m[cNM], g_pos_u[cNU], g_pos_m[cNM];
__device__ int g_off_u[cNU + 1], g_off_m[cNM + 1];
__device__ int g_adj_u[cE], g_adj_m[cE];
__device__ int g_aux[128];
__device__ double g_stats[192];
__device__ float g_bnp[192];
__device__ float g_wfu[192 * 64], g_wfm[192 * 64], g_bfu[64], g_bfm[64];

constexpr int CNTB = (cE + 255) / 256;          // 3907
constexpr int GATB = (cNU * 16 + 255) / 256;    // 6250
constexpr int MB = (cNM + 127) / 128;           // 157
constexpr int UB = (cNU + 127) / 128;           // 782

__global__ void zero_kernel() {
    int i = blockIdx.x * blockDim.x + threadIdx.x;
    if (i < cNU) { g_cnt_u[i] = 0; g_pos_u[i] = 0; }
    if (i < cNM) { g_cnt_m[i] = 0; g_pos_m[i] = 0; }
    if (i < 192) g_stats[i] = 0.0;
}

// count + gather_u0 + wfuse in one launch (independent work, no dyn smem)
__global__ void __launch_bounds__(256) prep_kernel(
    const int* __restrict__ eu, const int* __restrict__ em,
    const int* __restrict__ n_id, const float* __restrict__ ue,
    const float* __restrict__ puW, const float* __restrict__ pub,
    const float* __restrict__ pmW, const float* __restrict__ pmb,
    const float* __restrict__ W1, const float* __restrict__ b1) {
    int bid = blockIdx.x, tid = threadIdx.x;
    if (bid < CNTB) {
        int e = bid * 256 + tid;
        if (e < cE) { atomicAdd(&g_cnt_u[eu[e]], 1); atomicAdd(&g_cnt_m[em[e]], 1); }
    } else if (bid < CNTB + GATB) {
        int i = (bid - CNTB) * 256 + tid;
        if (i < cNU * 16) {
            int r = i >> 4, c = i & 15;
            ((float4*)g_xu0)[r * 16 + c] = ((const float4*)ue)[(size_t)n_id[r] * 16 + c];
        }
    } else {
        int b = bid - CNTB - GATB;  // 0..384
        int c = tid;
        if (c < 64) {
            if (b < 192) {
                float s = 0.f;
                for (int k = 0; k < 64; ++k) s += puW[b * 64 + k] * W1[k * 64 + c];
                g_wfu[b * 64 + c] = s;
            } else if (b < 384) {
                int r = b - 192;
                float s = 0.f;
                for (int k = 0; k < 64; ++k) s += pmW[r * 64 + k] * W1[(64 + k) * 64 + c];
                g_wfm[r * 64 + c] = s;
            } else {
                float su = 0.f, sm2 = 0.f;
                for (int k = 0; k < 64; ++k) {
                    su += pub[k] * W1[k * 64 + c];
                    sm2 += pmb[k] * W1[(64 + k) * 64 + c];
                }
                g_bfu[c] = su + b1[c];
                g_bfm[c] = sm2;
            }
        }
    }
}

__global__ void __launch_bounds__(1024) scan1_kernel() {
    __shared__ int s[1024];
    int b = blockIdx.x, t = threadIdx.x;
    const int* cnt; int* off; int n, base;
    if (b < NBU) { cnt = g_cnt_u; off = g_off_u; n = cNU; base = b * 1024; }
    else         { cnt = g_cnt_m; off = g_off_m; n = cNM; base = (b - NBU) * 1024; }
    int i = base + t;
    int v = (i < n) ? cnt[i] : 0;
    int x = v;
    for (int d = 1; d < 1024; d <<= 1) {
        s[t] = x; __syncthreads();
        if (t >= d) x += s[t - d];
        __syncthreads();
    }
    if (i < n) off[i] = x - v;
    if (t == 1023) g_aux[b] = x;
}

// scan3 also does scan2's job: per-thread prefix over <=118 aux values
__global__ void scan3_kernel() {
    int i = blockIdx.x * blockDim.x + threadIdx.x;
    if (i < cNU) {
        int k = i >> 10;
        int p = 0;
        for (int j = 0; j < k; ++j) p += g_aux[j];
        g_off_u[i] += p;
    }
    int jj = i - cNU;
    if (jj >= 0 && jj < cNM) {
        int k = jj >> 10;
        int p = 0;
        for (int j = 0; j < k; ++j) p += g_aux[NBU + j];
        g_off_m[jj] += p;
    }
    if (i == 0) { g_off_u[cNU] = cE; g_off_m[cNM] = cE; }
}

__global__ void fill_kernel(const int* __restrict__ eu, const int* __restrict__ em) {
    int e = blockIdx.x * blockDim.x + threadIdx.x;
    if (e < cE) {
        int u = eu[e], m = em[e];
        g_adj_m[g_off_m[m] + atomicAdd(&g_pos_m[m], 1)] = u;
        g_adj_u[g_off_u[u] + atomicAdd(&g_pos_u[u], 1)] = m;
    }
}

__device__ __forceinline__ void agg_row(const float* __restrict__ src, int lds,
                                        const int* __restrict__ adj, int beg, int end,
                                        float* __restrict__ dst, int lane) {
    float ax = 0.f, ay = 0.f;
#pragma unroll 4
    for (int e = beg; e < end; ++e) {
        int s = __ldg(adj + e);
        float2 v = *(const float2*)(src + (size_t)s * lds + lane * 2);
        ax += v.x; ay += v.y;
    }
    float inv = (end > beg) ? 1.f / (float)(end - beg) : 0.f;
    *(float2*)(dst + lane * 2) = make_float2(ax * inv, ay * inv);
}

// both directions in one zero-smem launch: warps [0,cNM) movie-dst, rest user-dst
__global__ void __launch_bounds__(256) agg_both_kernel(const float* __restrict__ xu_src, int ldu) {
    int w = (blockIdx.x * blockDim.x + threadIdx.x) >> 5;
    int lane = threadIdx.x & 31;
    if (w < cNM) {
        agg_row(xu_src, ldu, g_adj_m, g_off_m[w], g_off_m[w + 1], g_agg_m + (size_t)w * 64, lane);
    } else {
        w -= cNM;
        if (w >= cNU) return;
        agg_row(g_ym, 64, g_adj_u, g_off_u[w], g_off_u[w + 1], g_agg_u + (size_t)w * 64, lane);
    }
}

// ---- uniform 50KB GEMM machinery: K processed in 64-wide chunks ----
constexpr int U64_SMEM = (128 * 66) * 4 + 32 * 64 * 8;   // 50176 -> 4 CTAs/SM
constexpr int Z2_SMEM  = (128 * 66) * 4 + 32 * 32 * 8;   // 41984

template <int N>
__device__ __forceinline__ void stageWpair64(float2* sWp, const float* __restrict__ W, int tid) {
    constexpr int NITEMS = 32 * (N / 4);
    for (int idx = tid; idx < NITEMS; idx += 256) {
        int k2 = idx / (N / 4);
        int j4 = (idx - k2 * (N / 4)) * 4;
        float4 r0 = *(const float4*)(W + (size_t)(2 * k2) * N + j4);
        float4 r1 = *(const float4*)(W + (size_t)(2 * k2 + 1) * N + j4);
        float2* d = sWp + k2 * N + j4;
        d[0] = make_float2(r0.x, r1.x);
        d[1] = make_float2(r0.y, r1.y);
        d[2] = make_float2(r0.z, r1.z);
        d[3] = make_float2(r0.w, r1.w);
    }
}

__device__ __forceinline__ void stageA64(float* sA, const float* __restrict__ x, int ldx,
                                         int rowbase, int nrows, int tid) {
    for (int idx = tid; idx < 128 * 32; idx += 256) {
        int r = idx >> 5, c2 = idx & 31, g = rowbase + r, c = c2 * 2;
        float2 v = make_float2(0.f, 0.f);
        if (g < nrows) v = *(const float2*)(x + (size_t)g * ldx + c);
        *(float2*)(sA + r * 66 + c) = v;
    }
}

// one 64-K FFMA2 pass accumulating into float acc[4][N/8]
template <int N>
__device__ __forceinline__ void gemm64_add(const float* __restrict__ sA,
                                           const float2* __restrict__ sWp,
                                           float acc[4][N / 8]) {
    constexpr int LDA = 66, CPT = N / 8;
    const int rowg = threadIdx.x & 31, colg = threadIdx.x >> 5;
    const float* aB = sA + rowg * LDA;
    const float2* wB = sWp + colg * CPT;
    unsigned long long accp[4][CPT];
#pragma unroll
    for (int i = 0; i < 4; ++i)
#pragma unroll
        for (int j = 0; j < CPT; ++j) accp[i][j] = 0ull;
#pragma unroll 4
    for (int k2 = 0; k2 < 32; ++k2) {
        unsigned long long a[4], w[CPT];
#pragma unroll
        for (int i = 0; i < 4; ++i)
            a[i] = *(const unsigned long long*)(aB + i * 32 * LDA + k2 * 2);
#pragma unroll
        for (int j = 0; j < CPT; ++j)
            w[j] = *(const unsigned long long*)(wB + k2 * N + j);
#pragma unroll
        for (int i = 0; i < 4; ++i)
#pragma unroll
            for (int j = 0; j < CPT; ++j)
                asm("fma.rn.f32x2 %0, %1, %2, %0;" : "+l"(accp[i][j]) : "l"(a[i]), "l"(w[j]));
    }
#pragma unroll
    for (int i = 0; i < 4; ++i)
#pragma unroll
        for (int j = 0; j < CPT; ++j) {
            unsigned int lo = (unsigned int)accp[i][j];
            unsigned int hi = (unsigned int)(accp[i][j] >> 32);
            acc[i][j] += __uint_as_float(lo) + __uint_as_float(hi);
        }
}

// stage + compute one chunk (barriers make smem reuse safe)
__device__ __forceinline__ void gemm64_pass(float* sA, float2* sWp,
                                            const float* __restrict__ x, int ldx,
                                            int rowbase, int nrows,
                                            const float* __restrict__ W,
                                            float acc[4][8], int tid) {
    stageWpair64<64>(sWp, W, tid);
    stageA64(sA, x, ldx, rowbase, nrows, tid);
    __syncthreads();
    gemm64_add<64>(sA, sWp, acc);
    __syncthreads();
}

// Y = x_m @ Wl (single chunk)
__global__ void __launch_bounds__(256) linear64_kernel(const float* __restrict__ x, int ldx,
                                                       const float* __restrict__ W) {
    extern __shared__ float sm[];
    float* sA = sm;
    float2* sWp = (float2*)(sm + 128 * 66);
    const int tid = threadIdx.x, rowbase = blockIdx.x * 128;
    float acc[4][8];
#pragma unroll
    for (int i = 0; i < 4; ++i)
#pragma unroll
        for (int j = 0; j < 8; ++j) acc[i][j] = 0.f;
    gemm64_pass(sA, sWp, x, ldx, rowbase, cNM, W, acc, tid);
    const int rowg = tid & 31, colg = tid >> 5;
#pragma unroll
    for (int i = 0; i < 4; ++i) {
        int g = rowbase + rowg + 32 * i;
        if (g < cNM) {
            float* dst = g_ym + (size_t)g * 64 + colg * 8;
            *(float4*)dst = make_float4(acc[i][0], acc[i][1], acc[i][2], acc[i][3]);
            *(float4*)(dst + 4) = make_float4(acc[i][4], acc[i][5], acc[i][6], acc[i][7]);
        }
    }
}

// fused SAGE: blocks [0,MB) movie (2 chunks), [MB,MB+UB) user (1 chunk) — all 50KB
__global__ void __launch_bounds__(256) sage_both_kernel(
    const float* __restrict__ xm, int ldm, const float* __restrict__ xu, int ldu,
    const float* __restrict__ Wl_um, const float* __restrict__ Wr_um,
    const float* __restrict__ b_um,
    const float* __restrict__ Wr_mu, const float* __restrict__ b_mu,
    float* __restrict__ out_m, float* __restrict__ out_u) {
    extern __shared__ float sm[];
    float* sA = sm;
    float2* sWp = (float2*)(sm + 128 * 66);
    __shared__ float sB[64];
    const int tid = threadIdx.x;
    const int rowg = tid & 31, colg = tid >> 5;
    float acc[4][8];
#pragma unroll
    for (int i = 0; i < 4; ++i)
#pragma unroll
        for (int j = 0; j < 8; ++j) acc[i][j] = 0.f;
    if ((int)blockIdx.x < MB) {
        const int rowbase = blockIdx.x * 128;
        if (tid < 64) sB[tid] = b_um[tid];
        gemm64_pass(sA, sWp, g_agg_m, 64, rowbase, cNM, Wl_um, acc, tid);
        gemm64_pass(sA, sWp, xm, ldm, rowbase, cNM, Wr_um, acc, tid);
#pragma unroll
        for (int i = 0; i < 4; ++i) {
            int g = rowbase + rowg + 32 * i;
            if (g < cNM) {
                float o[8];
#pragma unroll
                for (int j = 0; j < 8; ++j) o[j] = fmaxf(acc[i][j] + sB[colg * 8 + j], 0.f);
                float* dst = out_m + (size_t)g * 192 + colg * 8;
                *(float4*)dst = make_float4(o[0], o[1], o[2], o[3]);
                *(float4*)(dst + 4) = make_float4(o[4], o[5], o[6], o[7]);
            }
        }
    } else {
        const int rowbase = (blockIdx.x - MB) * 128;
        if (tid < 64) sB[tid] = b_mu[tid];
        gemm64_pass(sA, sWp, xu, ldu, rowbase, cNU, Wr_mu, acc, tid);
#pragma unroll
        for (int i = 0; i < 4; ++i) {
            int g = rowbase + rowg + 32 * i;
            if (g < cNU) {
                const float* ag = g_agg_u + (size_t)g * 64 + colg * 8;
                float4 a0 = *(const float4*)ag, a1 = *(const float4*)(ag + 4);
                float o[8];
                o[0] = fmaxf(acc[i][0] + a0.x + sB[colg * 8 + 0], 0.f);
                o[1] = fmaxf(acc[i][1] + a0.y + sB[colg * 8 + 1], 0.f);
                o[2] = fmaxf(acc[i][2] + a0.z + sB[colg * 8 + 2], 0.f);
                o[3] = fmaxf(acc[i][3] + a0.w + sB[colg * 8 + 3], 0.f);
                o[4] = fmaxf(acc[i][4] + a1.x + sB[colg * 8 + 4], 0.f);
                o[5] = fmaxf(acc[i][5] + a1.y + sB[colg * 8 + 5], 0.f);
                o[6] = fmaxf(acc[i][6] + a1.z + sB[colg * 8 + 6], 0.f);
                o[7] = fmaxf(acc[i][7] + a1.w + sB[colg * 8 + 7], 0.f);
                float* dst = out_u + (size_t)g * 192 + colg * 8;
                *(float4*)dst = make_float4(o[0], o[1], o[2], o[3]);
                *(float4*)(dst + 4) = make_float4(o[4], o[5], o[6], o[7]);
            }
        }
    }
}

// proj as 3 x 64-K chunks at 50KB: blocks [0,UB) users, [UB,UB+MB) movies
__global__ void __launch_bounds__(256) proj_gemm_kernel() {
    extern __shared__ float sm[];
    float* sA = sm;
    float2* sWp = (float2*)(sm + 128 * 66);
    __shared__ float sB[64];
    const int tid = threadIdx.x;
    bool isU = (int)blockIdx.x < UB;
    const float* A = isU ? g_cat_u : g_cat_m;
    const float* W = isU ? g_wfu : g_wfm;
    const float* bias = isU ? g_bfu : g_bfm;
    float* outp = isU ? g_hu : g_hm;
    int nrows = isU ? cNU : cNM;
    int rowbase = (isU ? blockIdx.x : (blockIdx.x - UB)) * 128;
    if (tid < 64) sB[tid] = bias[tid];
    float acc[4][8];
#pragma unroll
    for (int i = 0; i < 4; ++i)
#pragma unroll
        for (int j = 0; j < 8; ++j) acc[i][j] = 0.f;
#pragma unroll
    for (int ch = 0; ch < 3; ++ch)
        gemm64_pass(sA, sWp, A + ch * 64, 192, rowbase, nrows, W + ch * 64 * 64, acc, tid);
    const int rowg = tid & 31, colg = tid >> 5;
#pragma unroll
    for (int i = 0; i < 4; ++i) {
        int g = rowbase + rowg + 32 * i;
        if (g < nrows) {
            float o[8];
#pragma unroll
            for (int j = 0; j < 8; ++j) o[j] = acc[i][j] + sB[colg * 8 + j];
            float* dst = outp + (size_t)g * 64 + colg * 8;
            *(float4*)dst = make_float4(o[0], o[1], o[2], o[3]);
            *(float4*)(dst + 4) = make_float4(o[4], o[5], o[6], o[7]);
        }
    }
}

__global__ void __launch_bounds__(256) z1stats_kernel(const int* __restrict__ lu,
                                                      const int* __restrict__ lm) {
    __shared__ float sS[64], sQ[64];
    int tid = threadIdx.x;
    if (tid < 64) { sS[tid] = 0.f; sQ[tid] = 0.f; }
    __syncthreads();
    int lane = tid & 31;
    int gw = (blockIdx.x * 256 + tid) >> 5;
    int nw = gridDim.x * 8;
    float s0 = 0.f, s1 = 0.f, q0 = 0.f, q1 = 0.f;
    for (int r = gw; r < cEL; r += nw) {
        int u = __ldg(lu + r), m = __ldg(lm + r);
        float2 a = *(const float2*)(g_hu + (size_t)u * 64 + lane * 2);
        float2 b = *(const float2*)(g_hm + (size_t)m * 64 + lane * 2);
        float ox = a.x + b.x, oy = a.y + b.y;
        s0 += ox; s1 += oy; q0 += ox * ox; q1 += oy * oy;
    }
    atomicAdd(&sS[lane * 2], s0); atomicAdd(&sS[lane * 2 + 1], s1);
    atomicAdd(&sQ[lane * 2], q0); atomicAdd(&sQ[lane * 2 + 1], q1);
    __syncthreads();
    if (tid < 64) {
        atomicAdd(&g_stats[tid], (double)sS[tid]);
        atomicAdd(&g_stats[64 + tid], (double)sQ[tid]);
    }
}

__global__ void bn_finalize_kernel(int soff, int boff, int n,
                                   const float* __restrict__ gamma,
                                   const float* __restrict__ beta, float invc) {
    int t = threadIdx.x;
    if (t < n) {
        double m = g_stats[soff + t] * invc;
        double v = g_stats[soff + n + t] * invc - m * m;
        float sc = gamma[t] * rsqrtf((float)v + 1e-5f);
        g_bnp[boff + t] = sc;
        g_bnp[boff + n + t] = beta[t] - (float)m * sc;
    }
}

__global__ void __launch_bounds__(256) z2_kernel(const int* __restrict__ lu,
                                                 const int* __restrict__ lm,
                                                 const float* __restrict__ W2,
                                                 const float* __restrict__ bias) {
    extern __shared__ float sm[];
    float* sA = sm;
    float2* sWp = (float2*)(sm + 128 * 66);
    __shared__ float sB[32], sSc[64], sSh[64];
    __shared__ int sIU[128], sIM[128];
    const int tid = threadIdx.x, rowbase = blockIdx.x * 128;
    if (tid < 32) sB[tid] = bias[tid];
    if (tid < 64) { sSc[tid] = g_bnp[tid]; sSh[tid] = g_bnp[64 + tid]; }
    if (tid < 128) {
        int g = rowbase + tid;
        sIU[tid] = (g < cEL) ? __ldg(lu + g) : 0;
        sIM[tid] = (g < cEL) ? __ldg(lm + g) : 0;
    }
    stageWpair64<32>(sWp, W2, tid);
    __syncthreads();
    for (int idx = tid; idx < 128 * 32; idx += 256) {
        int r = idx >> 5, c2 = idx & 31, g = rowbase + r, c = c2 * 2;
        float2 v = make_float2(0.f, 0.f);
        if (g < cEL) {
            float2 a = *(const float2*)(g_hu + (size_t)sIU[r] * 64 + c);
            float2 b = *(const float2*)(g_hm + (size_t)sIM[r] * 64 + c);
            float zx = a.x + b.x, zy = a.y + b.y;
            v.x = fmaxf(zx * sSc[c] + sSh[c], 0.f);
            v.y = fmaxf(zy * sSc[c + 1] + sSh[c + 1], 0.f);
        }
        *(float2*)(sA + r * 66 + c) = v;
    }
    __syncthreads();
    float acc[4][4];
#pragma unroll
    for (int i = 0; i < 4; ++i)
#pragma unroll
        for (int j = 0; j < 4; ++j) acc[i][j] = 0.f;
    gemm64_add<32>(sA, sWp, acc);
    const int rowg = tid & 31, colg = tid >> 5;
    float ls[4] = {0}, lq[4] = {0};
#pragma unroll
    for (int i = 0; i < 4; ++i) {
        int g = rowbase + rowg + 32 * i;
        if (g < cEL) {
            float o[4];
#pragma unroll
            for (int j = 0; j < 4; ++j) {
                o[j] = acc[i][j] + sB[colg * 4 + j];
                ls[j] += o[j]; lq[j] += o[j] * o[j];
            }
            *(float4*)(g_z2 + (size_t)g * 32 + colg * 4) = make_float4(o[0], o[1], o[2], o[3]);
        }
    }
    __syncthreads();
#pragma unroll
    for (int j = 0; j < 4; ++j) {
        sA[rowg * 32 + colg * 4 + j] = ls[j];
        sA[1024 + rowg * 32 + colg * 4 + j] = lq[j];
    }
    __syncthreads();
    if (tid < 32) {
        float s = 0.f, q = 0.f;
        for (int g2 = 0; g2 < 32; ++g2) { s += sA[g2 * 32 + tid]; q += sA[1024 + g2 * 32 + tid]; }
        atomicAdd(&g_stats[128 + tid], (double)s);
        atomicAdd(&g_stats[160 + tid], (double)q);
    }
}

__global__ void __launch_bounds__(256) z3_kernel(const float* __restrict__ W3,
                                                 const float* __restrict__ b3,
                                                 float* __restrict__ out) {
    __shared__ float sW[32], sSc[32], sSh[32];
    int tid = threadIdx.x;
    if (tid < 32) { sW[tid] = W3[tid]; sSc[tid] = g_bnp[128 + tid]; sSh[tid] = g_bnp[160 + tid]; }
    __syncthreads();
    int g = blockIdx.x * 256 + tid;
    if (g < cEL) {
        const float* row = g_z2 + (size_t)g * 32;
        float acc = 0.f;
#pragma unroll
        for (int c = 0; c < 32; c += 4) {
            float4 v = *(const float4*)(row + c);
            acc += fmaxf(v.x * sSc[c] + sSh[c], 0.f) * sW[c];
            acc += fmaxf(v.y * sSc[c + 1] + sSh[c + 1], 0.f) * sW[c + 1];
            acc += fmaxf(v.z * sSc[c + 2] + sSh[c + 2], 0.f) * sW[c + 2];
            acc += fmaxf(v.w * sSc[c + 3] + sSh[c + 3], 0.f) * sW[c + 3];
        }
        out[g] = acc + b3[0];
    }
}

extern "C" void kernel_launch(void* const* d_in, const int* in_sizes, int n_in,
                              void* d_out, int out_size) {
    const int* n_id = (const int*)d_in[0];
    const float* movie_x = (const float*)d_in[1];
    const int* eu = (const int*)d_in[2];
    const int* em = (const int*)d_in[3];
    const int* lu = (const int*)d_in[4];
    const int* lm = (const int*)d_in[5];
    const float* user_emb = (const float*)d_in[6];
    const float* Wl_um = (const float*)d_in[7];
    const float* b_um = (const float*)d_in[8];
    const float* Wr_um = (const float*)d_in[9];
    const float* Wl_mu = (const float*)d_in[10];
    const float* b_mu = (const float*)d_in[11];
    const float* Wr_mu = (const float*)d_in[12];
    const float* proj_u_W = (const float*)d_in[13];
    const float* proj_u_b = (const float*)d_in[14];
    const float* proj_m_W = (const float*)d_in[15];
    const float* proj_m_b = (const float*)d_in[16];
    const float* W1 = (const float*)d_in[17];
    const float* b1 = (const float*)d_in[18];
    const float* g1 = (const float*)d_in[19];
    const float* be1 = (const float*)d_in[20];
    const float* W2 = (const float*)d_in[21];
    const float* b2 = (const float*)d_in[22];
    const float* g2 = (const float*)d_in[23];
    const float* be2 = (const float*)d_in[24];
    const float* W3 = (const float*)d_in[25];
    const float* b3 = (const float*)d_in[26];
    float* out = (float*)d_out;

    cudaFuncSetAttribute(linear64_kernel, cudaFuncAttributeMaxDynamicSharedMemorySize, U64_SMEM);
    cudaFuncSetAttribute(sage_both_kernel, cudaFuncAttributeMaxDynamicSharedMemorySize, U64_SMEM);
    cudaFuncSetAttribute(proj_gemm_kernel, cudaFuncAttributeMaxDynamicSharedMemorySize, U64_SMEM);
    cudaFuncSetAttribute(z2_kernel, cudaFuncAttributeMaxDynamicSharedMemorySize, Z2_SMEM);

    float* xu; cudaGetSymbolAddress((void**)&xu, g_xu0);
    float* cu; cudaGetSymbolAddress((void**)&cu, g_cat_u);
    float* cm; cudaGetSymbolAddress((void**)&cm, g_cat_m);

    zero_kernel<<<(cNU + 255) / 256, 256>>>();
    prep_kernel<<<CNTB + GATB + 385, 256>>>(eu, em, n_id, user_emb,
                                            proj_u_W, proj_u_b, proj_m_W, proj_m_b, W1, b1);
    scan1_kernel<<<NBU + NBM, 1024>>>();
    scan3_kernel<<<(cNU + cNM + 255) / 256, 256>>>();
    fill_kernel<<<(cE + 255) / 256, 256>>>(eu, em);

    const int AGGB = ((cNU + cNM) * 32 + 255) / 256;
    for (int i = 0; i < 3; ++i) {
        const float* xup = i ? (cu + (i - 1) * 64) : xu;
        const float* xmp = i ? (cm + (i - 1) * 64) : movie_x;
        int ldu = i ? 192 : 64, ldm = i ? 192 : 64;
        linear64_kernel<<<MB, 256, U64_SMEM>>>(xmp, ldm, Wl_mu + i * 4096);
        agg_both_kernel<<<AGGB, 256>>>(xup, ldu);
        sage_both_kernel<<<MB + UB, 256, U64_SMEM>>>(
            xmp, ldm, xup, ldu, Wl_um + i * 4096, Wr_um + i * 4096, b_um + i * 64,
            Wr_mu + i * 4096, b_mu + i * 64, cm + i * 64, cu + i * 64);
    }
    proj_gemm_kernel<<<UB + MB, 256, U64_SMEM>>>();

    z1stats_kernel<<<1184, 256>>>(lu, lm);
    bn_finalize_kernel<<<1, 64>>>(0, 0, 64, g1, be1, 1.f / cEL);
    z2_kernel<<<(cEL + 127) / 128, 256, Z2_SMEM>>>(lu, lm, W2, b2);
    bn_finalize_kernel<<<1, 64>>>(128, 128, 32, g2, be2, 1.f / cEL);
    z3_kernel<<<(cEL + 255) / 256, 256>>>(W3, b3, out);
}